// round 11
// baseline (speedup 1.0000x reference)
#include <cuda_runtime.h>
#include <cstdint>

// B=4, M_IN=16, M_OUT=32, C=32.  x:(4,16,32,32,32,32) fp32 -> out:(4,32,4,32) fp32
//
//   s1[b,m,c2] = sum_{c3,c4,c5} x          (s2 == s1)
//   s3[b,m,c3] = sum_{c2,c4,c5} x
//   s4[b,m,c4] = sum_{c2,c3,c5} x
//   W = alpha+beta+gamma+delta (16x32)
//   out[b,n,i,c] = sum_m S_i[b,m,c] * W[m,n],  S = [s1,s1,s3,s4]
//
// Kernel 1 (4096 blocks): half-slice stream. Hot loop is now PURE
//   (8 LDG.128 -> 24 addx2 -> repeat): all shuffle reductions deferred to
//   the epilogue (row chains interleaved), s1 derived from s4 column sums.
//   Epilogue REDG-accumulates into g_S (R10-proven neutral for the stream).
// Kernel 2 (16 blocks): pure einsum from L2-hot g_S, self-zeroing (R10).

__device__ float g_S[8192];              // [bm][i][c], REDG-accumulated

__device__ __forceinline__ unsigned long long addx2(unsigned long long a,
                                                    unsigned long long b) {
    unsigned long long r;
    asm("add.rn.f32x2 %0, %1, %2;" : "=l"(r) : "l"(a), "l"(b));
    return r;
}
__device__ __forceinline__ float x2sum(unsigned long long a) {
    unsigned lo, hi;
    asm("mov.b64 {%0,%1}, %2;" : "=r"(lo), "=r"(hi) : "l"(a));
    return __uint_as_float(lo) + __uint_as_float(hi);
}
// evict-first 16B streaming load (read-once data; keep L2 for partials)
__device__ __forceinline__ ulonglong2 ldcs2(const ulonglong2* p) {
    ulonglong2 r;
    asm("ld.global.cs.v2.u64 {%0, %1}, [%2];" : "=l"(r.x), "=l"(r.y) : "l"(p));
    return r;
}
// fire-and-forget float accumulate (REDG: no return, no wait)
__device__ __forceinline__ void red_add(float* p, float v) {
    asm volatile("red.global.add.f32 [%0], %1;" :: "l"(p), "f"(v) : "memory");
}

// ---------------- Kernel 1: half-slice reduction, pure hot loop ----------------
__global__ void __launch_bounds__(256, 4)
k_reduce(const float* __restrict__ x) {
    const int t    = threadIdx.x;
    const int lane = t & 31;
    const int w    = t >> 5;
    const int bid  = blockIdx.x;          // half-slice id
    const int slice = bid >> 1;
    const int half  = bid & 1;
    const int bm    = bid >> 6;

    const ulonglong2* __restrict__ xv =
        reinterpret_cast<const ulonglong2*>(x) + (size_t)bid * 4096; // 16384 floats

    __shared__ float s4buf[256];          // [warp][c4]

    unsigned long long col[8];
#pragma unroll
    for (int s = 0; s < 8; ++s) col[s] = 0ull;
    unsigned long long row0 = 0ull, row1 = 0ull;

    // ---- hot loop: row k=w then k=w+8; nothing but loads and packed adds ----
    {
        const ulonglong2* __restrict__ p = xv + w * 256 + lane;
        ulonglong2 d[8];
#pragma unroll
        for (int s = 0; s < 8; ++s) d[s] = ldcs2(p + s * 32);
#pragma unroll
        for (int s = 0; s < 8; ++s) {
            unsigned long long v = addx2(d[s].x, d[s].y);
            row0   = addx2(row0, v);
            col[s] = addx2(col[s], v);
        }
    }
    {
        const ulonglong2* __restrict__ p = xv + (w + 8) * 256 + lane;
        ulonglong2 d[8];
#pragma unroll
        for (int s = 0; s < 8; ++s) d[s] = ldcs2(p + s * 32);
#pragma unroll
        for (int s = 0; s < 8; ++s) {
            unsigned long long v = addx2(d[s].x, d[s].y);
            row1   = addx2(row1, v);
            col[s] = addx2(col[s], v);
        }
    }

    // ---- epilogue: interleaved row shuffle chains -> s3 REDG ----
    float r0 = x2sum(row0);
    float r1 = x2sum(row1);
#pragma unroll
    for (int o = 16; o; o >>= 1) {
        r0 += __shfl_down_sync(0xffffffffu, r0, o);
        r1 += __shfl_down_sync(0xffffffffu, r1, o);
    }
    if (lane == 0) {
        red_add(&g_S[bm * 128 + 64 + half * 16 + w],     r0);   // s3[c3=half*16+w]
        red_add(&g_S[bm * 128 + 64 + half * 16 + w + 8], r1);   // s3[c3=half*16+w+8]
    }

    // ---- column (c4) octet folds -> per-warp s4 partials in smem ----
#pragma unroll
    for (int s = 0; s < 8; ++s) {
        float cs = x2sum(col[s]);
        cs += __shfl_down_sync(0xffffffffu, cs, 4);
        cs += __shfl_down_sync(0xffffffffu, cs, 2);
        cs += __shfl_down_sync(0xffffffffu, cs, 1);
        if ((lane & 7) == 0) s4buf[w * 32 + s * 4 + (lane >> 3)] = cs;
    }
    __syncthreads();

    if (t < 32) {        // warp 0: cross-warp s4 fold; block total from col sums
        float v = 0.f;
#pragma unroll
        for (int ww = 0; ww < 8; ++ww) v += s4buf[ww * 32 + t];
        red_add(&g_S[bm * 128 + 96 + t], v);            // s4[c4=t]
        float tot = v;                                  // sum_{c4} v = half-slice total
#pragma unroll
        for (int o = 16; o; o >>= 1) tot += __shfl_down_sync(0xffffffffu, tot, o);
        if (t == 0) {
            const int c2 = slice & 31;
            red_add(&g_S[bm * 128 +      c2], tot);     // s1[c2]
            red_add(&g_S[bm * 128 + 32 + c2], tot);     // s2 == s1
        }
    }
}

// ---------------- Kernel 2: pure einsum, grid 16 = (b,i), self-zeroing (R10) ----------------
__global__ void __launch_bounds__(256)
k_einsum(const float* __restrict__ a, const float* __restrict__ bb,
         const float* __restrict__ g, const float* __restrict__ d,
         float* __restrict__ out) {
    __shared__ float sS[512];             // [m][c] for this (b,i)
    __shared__ float sW[512];             // [m][n]

    const int t   = threadIdx.x;
    const int bid = blockIdx.x;
    const int b   = bid >> 2;
    const int i   = bid & 3;

    sW[t]       = a[t]       + bb[t]       + g[t]       + d[t];
    sW[t + 256] = a[t + 256] + bb[t + 256] + g[t + 256] + d[t + 256];

    // snapshot S[b, m, i, c] -> smem (2 values per thread)
    const int e0 = t, e1 = t + 256;       // e = m*32 + c
    float* p0 = &g_S[(b * 16 + (e0 >> 5)) * 128 + i * 32 + (e0 & 31)];
    float* p1 = &g_S[(b * 16 + (e1 >> 5)) * 128 + i * 32 + (e1 & 31)];
    sS[e0] = *p0;
    sS[e1] = *p1;
    __syncthreads();

    // self-zero for the next graph replay (reads snapshotted above)
    *p0 = 0.f;
    *p1 = 0.f;

    // thread computes 4 outputs: c = t&31, n = (t>>5) + 8*nn
    const int c  = t & 31;
    const int n0 = t >> 5;
#pragma unroll
    for (int nn = 0; nn < 4; ++nn) {
        const int n = n0 + 8 * nn;
        float acc = 0.f;
#pragma unroll
        for (int m = 0; m < 16; ++m)
            acc += sS[m * 32 + c] * sW[m * 32 + n];
        out[((b * 32 + n) * 4 + i) * 32 + c] = acc;
    }
}

// ---------------- launch ----------------
extern "C" void kernel_launch(void* const* d_in, const int* in_sizes, int n_in,
                              void* d_out, int out_size) {
    const float* x     = (const float*)d_in[0];
    const float* alpha = (const float*)d_in[1];
    const float* beta  = (const float*)d_in[2];
    const float* gamma = (const float*)d_in[3];
    const float* delta = (const float*)d_in[4];

    k_reduce<<<4096, 256>>>(x);
    k_einsum<<<16, 256>>>(alpha, beta, gamma, delta, (float*)d_out);
}

// round 12
// speedup vs baseline: 1.0307x; 1.0307x over previous
#include <cuda_runtime.h>
#include <cstdint>

// B=4, M_IN=16, M_OUT=32, C=32.  x:(4,16,32,32,32,32) fp32 -> out:(4,32,4,32) fp32
//
//   s1[b,m,c2] = sum_{c3,c4,c5} x          (s2 == s1)
//   s3[b,m,c3] = sum_{c2,c4,c5} x
//   s4[b,m,c4] = sum_{c2,c3,c5} x
//   W = alpha+beta+gamma+delta (16x32)
//   out[b,n,i,c] = sum_m S_i[b,m,c] * W[m,n],  S = [s1,s1,s3,s4]
//
// Kernel 1 (4096 blocks): R10-proven hot loop + REDG epilogue into g_S.
//   Block 0 ALSO precomputes g_W = a+b+g+d (runs in wave 1, so g_W is
//   L2-hot ~35us before the tail reads it).
// Kernel 2 (16 blocks): einsum reading ONLY L2-hot g_W + g_S (no cold DRAM
//   on the critical path), self-zeroing g_S for graph replay.

__device__ float g_S[8192];              // [bm][i][c], REDG-accumulated
__device__ float g_W[512];               // [m][n] = a+b+g+d, written by block 0

__device__ __forceinline__ unsigned long long addx2(unsigned long long a,
                                                    unsigned long long b) {
    unsigned long long r;
    asm("add.rn.f32x2 %0, %1, %2;" : "=l"(r) : "l"(a), "l"(b));
    return r;
}
__device__ __forceinline__ float x2sum(unsigned long long a) {
    unsigned lo, hi;
    asm("mov.b64 {%0,%1}, %2;" : "=r"(lo), "=r"(hi) : "l"(a));
    return __uint_as_float(lo) + __uint_as_float(hi);
}
// evict-first 16B streaming load (read-once data; keep L2 for partials)
__device__ __forceinline__ ulonglong2 ldcs2(const ulonglong2* p) {
    ulonglong2 r;
    asm("ld.global.cs.v2.u64 {%0, %1}, [%2];" : "=l"(r.x), "=l"(r.y) : "l"(p));
    return r;
}
// fire-and-forget float accumulate (REDG: no return, no wait)
__device__ __forceinline__ void red_add(float* p, float v) {
    asm volatile("red.global.add.f32 [%0], %1;" :: "l"(p), "f"(v) : "memory");
}

// ---------------- Kernel 1: half-slice reduction (R10 hot loop, verbatim) ----------------
__global__ void __launch_bounds__(256, 4)
k_reduce(const float* __restrict__ x,
         const float* __restrict__ wa, const float* __restrict__ wb,
         const float* __restrict__ wg, const float* __restrict__ wd) {
    const int t    = threadIdx.x;
    const int lane = t & 31;
    const int w    = t >> 5;
    const int bid  = blockIdx.x;          // half-slice id
    const int slice = bid >> 1;
    const int half  = bid & 1;
    const int bm    = bid >> 6;

    // block 0: precompute W sum early (wave 1) so the tail reads it L2-hot
    if (bid == 0) {
        g_W[t]       = wa[t]       + wb[t]       + wg[t]       + wd[t];
        g_W[t + 256] = wa[t + 256] + wb[t + 256] + wg[t + 256] + wd[t + 256];
    }

    const ulonglong2* __restrict__ xv =
        reinterpret_cast<const ulonglong2*>(x) + (size_t)bid * 4096; // 16384 floats

    __shared__ float s4buf[256];          // [warp][c4]
    __shared__ float wt[8];

    unsigned long long col[8];
#pragma unroll
    for (int s = 0; s < 8; ++s) col[s] = 0ull;

    float rows_tot = 0.f;                 // valid on lane 0
#pragma unroll
    for (int j = 0; j < 2; ++j) {
        const int k = w + j * 8;          // local row 0..15  (c3 = half*16 + k)
        const ulonglong2* __restrict__ p = xv + k * 256 + lane;

        ulonglong2 d[8];
#pragma unroll
        for (int s = 0; s < 8; ++s) d[s] = ldcs2(p + s * 32);   // 8 back-to-back LDG.128

        unsigned long long row = 0ull;
#pragma unroll
        for (int s = 0; s < 8; ++s) {
            unsigned long long v = addx2(d[s].x, d[s].y);  // {f0+f2, f1+f3}
            row    = addx2(row, v);
            col[s] = addx2(col[s], v);
        }
        float r = x2sum(row);
#pragma unroll
        for (int o = 16; o; o >>= 1) r += __shfl_down_sync(0xffffffffu, r, o);
        if (lane == 0) {
            red_add(&g_S[bm * 128 + 64 + half * 16 + k], r);    // s3[c3]
            rows_tot += r;
        }
    }

    // fold column accs: lanes in an octet share c4 = s*4 + (lane>>3)
#pragma unroll
    for (int s = 0; s < 8; ++s) {
        float cs = x2sum(col[s]);
        cs += __shfl_down_sync(0xffffffffu, cs, 4);
        cs += __shfl_down_sync(0xffffffffu, cs, 2);
        cs += __shfl_down_sync(0xffffffffu, cs, 1);
        if ((lane & 7) == 0) s4buf[w * 32 + s * 4 + (lane >> 3)] = cs;
    }
    if (lane == 0) wt[w] = rows_tot;
    __syncthreads();

    if (t < 32) {        // warp 0: cross-warp s4 fold -> REDG; block total -> s1
        float v = 0.f;
#pragma unroll
        for (int ww = 0; ww < 8; ++ww) v += s4buf[ww * 32 + t];
        red_add(&g_S[bm * 128 + 96 + t], v);            // s4[c4=t]
        if (t == 0) {
            float s = 0.f;
#pragma unroll
            for (int ww = 0; ww < 8; ++ww) s += wt[ww];
            const int c2 = slice & 31;
            red_add(&g_S[bm * 128 +      c2], s);       // s1[c2]
            red_add(&g_S[bm * 128 + 32 + c2], s);       // s2 == s1
        }
    }
}

// ---------------- Kernel 2: einsum from L2-hot g_W/g_S, grid 16 = (b,i) ----------------
__global__ void __launch_bounds__(256)
k_einsum(float* __restrict__ out) {
    __shared__ float sS[512];             // [m][c] for this (b,i)
    __shared__ float sW[512];             // [m][n]

    const int t   = threadIdx.x;
    const int bid = blockIdx.x;
    const int b   = bid >> 2;
    const int i   = bid & 3;

    // all L2-hot: g_W written in wave 1 of k_reduce, g_S REDG'd there too
    sW[t]       = g_W[t];
    sW[t + 256] = g_W[t + 256];

    const int e0 = t, e1 = t + 256;       // e = m*32 + c
    float* p0 = &g_S[(b * 16 + (e0 >> 5)) * 128 + i * 32 + (e0 & 31)];
    float* p1 = &g_S[(b * 16 + (e1 >> 5)) * 128 + i * 32 + (e1 & 31)];
    sS[e0] = *p0;
    sS[e1] = *p1;
    __syncthreads();

    // self-zero for the next graph replay (reads snapshotted above)
    *p0 = 0.f;
    *p1 = 0.f;

    // thread computes 4 outputs: c = t&31, n = (t>>5) + 8*nn
    const int c  = t & 31;
    const int n0 = t >> 5;
#pragma unroll
    for (int nn = 0; nn < 4; ++nn) {
        const int n = n0 + 8 * nn;
        float acc = 0.f;
#pragma unroll
        for (int m = 0; m < 16; ++m)
            acc += sS[m * 32 + c] * sW[m * 32 + n];
        out[((b * 32 + n) * 4 + i) * 32 + c] = acc;
    }
}

// ---------------- launch ----------------
extern "C" void kernel_launch(void* const* d_in, const int* in_sizes, int n_in,
                              void* d_out, int out_size) {
    const float* x     = (const float*)d_in[0];
    const float* alpha = (const float*)d_in[1];
    const float* beta  = (const float*)d_in[2];
    const float* gamma = (const float*)d_in[3];
    const float* delta = (const float*)d_in[4];

    k_reduce<<<4096, 256>>>(x, alpha, beta, gamma, delta);
    k_einsum<<<16, 256>>>((float*)d_out);
}